// round 1
// baseline (speedup 1.0000x reference)
#include <cuda_runtime.h>

#define B_  16384
#define T_  128
#define E_  20
#define H_  20
#define L_  15

// 2 lanes per batch row: lane parity 'half' owns hidden units [half*10, half*10+10).
// Weights live in shared memory, transposed so the K-loop is contiguous (LDS.128).
__global__ __launch_bounds__(64) void wordvanilla_rnn_kernel(
    const int*   __restrict__ x,      // [B, T]
    const float* __restrict__ drop,   // [1]
    const float* __restrict__ emb,    // [V, E]
    const float* __restrict__ Wxh,    // [E, H]
    const float* __restrict__ Whh,    // [H, H]
    const float* __restrict__ bh,     // [H]
    const float* __restrict__ Wd,     // [H, L]
    const float* __restrict__ bd,     // [L]
    float*       __restrict__ out)    // [B, L]
{
    __shared__ float sWxhT[H_][E_];   // sWxhT[j][k] = Wxh[k][j]
    __shared__ float sWhhT[H_][H_];   // sWhhT[j][i] = Whh[i][j]
    __shared__ float sWdT[L_][H_];    // sWdT[l][i]  = Wd[i][l]
    __shared__ float sbh[H_];
    __shared__ float sbd[16];

    const int tid = threadIdx.x;
    for (int idx = tid; idx < H_ * E_; idx += 64) {
        int j = idx / E_, k = idx % E_;
        sWxhT[j][k] = Wxh[k * H_ + j];
        sWhhT[j][k] = Whh[k * H_ + j];
    }
    for (int idx = tid; idx < L_ * H_; idx += 64) {
        int l = idx / H_, i = idx % H_;
        sWdT[l][i] = Wd[i * L_ + l];
    }
    if (tid < H_) sbh[tid] = bh[tid];
    if (tid < L_) sbd[tid] = bd[tid];
    __syncthreads();

    const int g    = blockIdx.x * 64 + tid;
    const int p    = g >> 1;        // batch row
    const int half = g & 1;         // which 10 hidden units this lane owns
    if (p >= B_) return;            // grid is exact; never taken
    const int j0 = half * 10;

    const int* xrow = x + (long)p * T_;

    float h[10];
    #pragma unroll
    for (int i = 0; i < 10; i++) h[i] = 0.0f;

    // Two-deep prefetch pipeline: token 2 ahead, embedding row 1 ahead.
    int tok_cur  = xrow[0];
    int tok_next = xrow[1];
    float4 ev4[5];
    {
        const float4* er = (const float4*)(emb + (long)tok_cur * E_);
        #pragma unroll
        for (int q = 0; q < 5; q++) ev4[q] = er[q];
    }

    #pragma unroll 1
    for (int t = 0; t < T_; t++) {
        const int tnn    = (t + 2 < T_) ? (t + 2) : (T_ - 1);
        const int tok_nn = xrow[tnn];
        float4 en4[5];
        {
            const float4* er = (const float4*)(emb + (long)tok_next * E_);
            #pragma unroll
            for (int q = 0; q < 5; q++) en4[q] = er[q];
        }

        float ev[20];
        #pragma unroll
        for (int q = 0; q < 5; q++) {
            ev[4*q+0] = ev4[q].x; ev[4*q+1] = ev4[q].y;
            ev[4*q+2] = ev4[q].z; ev[4*q+3] = ev4[q].w;
        }

        // acc = bh + e . Wxh   (my 10 output columns)
        float acc[10];
        #pragma unroll
        for (int jj = 0; jj < 10; jj++) {
            float a = sbh[j0 + jj];
            const float* row = sWxhT[j0 + jj];
            #pragma unroll
            for (int k = 0; k < E_; k++) a = fmaf(ev[k], row[k], a);
            acc[jj] = a;
        }

        // Exchange hidden halves with partner lane; normalize to canonical order.
        float oth[10];
        #pragma unroll
        for (int i = 0; i < 10; i++) oth[i] = __shfl_xor_sync(0xffffffffu, h[i], 1);
        float hA[10], hB[10];   // hA = h[0..9] global, hB = h[10..19] global
        #pragma unroll
        for (int i = 0; i < 10; i++) {
            hA[i] = half ? oth[i] : h[i];
            hB[i] = half ? h[i]   : oth[i];
        }

        // acc += h . Whh ; h = tanh(acc)
        #pragma unroll
        for (int jj = 0; jj < 10; jj++) {
            float a = acc[jj];
            const float* row = sWhhT[j0 + jj];
            #pragma unroll
            for (int i = 0; i < 10; i++) a = fmaf(hA[i], row[i],      a);
            #pragma unroll
            for (int i = 0; i < 10; i++) a = fmaf(hB[i], row[10 + i], a);
            // tanh(a) = 1 - 2/(exp(2a)+1): saturates correctly at +/-inf
            const float ex = __expf(2.0f * a);
            h[jj] = 1.0f - __fdividef(2.0f, ex + 1.0f);
        }

        #pragma unroll
        for (int q = 0; q < 5; q++) ev4[q] = en4[q];
        tok_next = tok_nn;
    }

    // Final exchange + epilogue (even lane computes the full softmax row)
    float oth[10];
    #pragma unroll
    for (int i = 0; i < 10; i++) oth[i] = __shfl_xor_sync(0xffffffffu, h[i], 1);

    if (half == 0) {
        const float sc = __fdividef(1.0f, 1.0f - drop[0]);  // inverted-dropout scale
        float hf[20];
        #pragma unroll
        for (int i = 0; i < 10; i++) { hf[i] = h[i] * sc; hf[10 + i] = oth[i] * sc; }

        float z[L_];
        #pragma unroll
        for (int l = 0; l < L_; l++) {
            float a = sbd[l];
            const float* row = sWdT[l];
            #pragma unroll
            for (int i = 0; i < H_; i++) a = fmaf(hf[i], row[i], a);
            z[l] = a;
        }
        float m = z[0];
        #pragma unroll
        for (int l = 1; l < L_; l++) m = fmaxf(m, z[l]);
        float s = 0.0f;
        #pragma unroll
        for (int l = 0; l < L_; l++) { z[l] = __expf(z[l] - m); s += z[l]; }
        const float inv = __fdividef(1.0f, s);
        float* o = out + (long)p * L_;
        #pragma unroll
        for (int l = 0; l < L_; l++) o[l] = z[l] * inv;
    }
}

extern "C" void kernel_launch(void* const* d_in, const int* in_sizes, int n_in,
                              void* d_out, int out_size)
{
    const int*   x    = (const int*)  d_in[0];
    const float* drop = (const float*)d_in[1];
    const float* emb  = (const float*)d_in[2];
    const float* Wxh  = (const float*)d_in[3];
    const float* Whh  = (const float*)d_in[4];
    const float* bh   = (const float*)d_in[5];
    const float* Wd   = (const float*)d_in[6];
    const float* bd   = (const float*)d_in[7];
    float* out = (float*)d_out;

    const int threads = 64;
    const int blocks  = (2 * B_) / threads;   // 512 blocks, exact
    wordvanilla_rnn_kernel<<<blocks, threads>>>(x, drop, emb, Wxh, Whh, bh, Wd, bd, out);
    (void)in_sizes; (void)n_in; (void)out_size;
}

// round 2
// speedup vs baseline: 1.0016x; 1.0016x over previous
#include <cuda_runtime.h>

#define B_  16384
#define T_  128
#define E_  20
#define H_  20
#define L_  15

// 2 lanes per batch row: lane parity 'half' owns hidden units [half*10, half*10+10).
// Weights live in shared memory, transposed so the K-loop is contiguous (LDS.128).
__global__ __launch_bounds__(64) void wordvanilla_rnn_kernel(
    const int*   __restrict__ x,      // [B, T]
    const float* __restrict__ drop,   // [1]
    const float* __restrict__ emb,    // [V, E]
    const float* __restrict__ Wxh,    // [E, H]
    const float* __restrict__ Whh,    // [H, H]
    const float* __restrict__ bh,     // [H]
    const float* __restrict__ Wd,     // [H, L]
    const float* __restrict__ bd,     // [L]
    float*       __restrict__ out)    // [B, L]
{
    __shared__ float sWxhT[H_][E_];   // sWxhT[j][k] = Wxh[k][j]
    __shared__ float sWhhT[H_][H_];   // sWhhT[j][i] = Whh[i][j]
    __shared__ float sWdT[L_][H_];    // sWdT[l][i]  = Wd[i][l]
    __shared__ float sbh[H_];
    __shared__ float sbd[16];

    const int tid = threadIdx.x;
    for (int idx = tid; idx < H_ * E_; idx += 64) {
        int j = idx / E_, k = idx % E_;
        sWxhT[j][k] = Wxh[k * H_ + j];
        sWhhT[j][k] = Whh[k * H_ + j];
    }
    for (int idx = tid; idx < L_ * H_; idx += 64) {
        int l = idx / H_, i = idx % H_;
        sWdT[l][i] = Wd[i * L_ + l];
    }
    if (tid < H_) sbh[tid] = bh[tid];
    if (tid < L_) sbd[tid] = bd[tid];
    __syncthreads();

    const int g    = blockIdx.x * 64 + tid;
    const int p    = g >> 1;        // batch row
    const int half = g & 1;         // which 10 hidden units this lane owns
    if (p >= B_) return;            // grid is exact; never taken
    const int j0 = half * 10;

    const int* xrow = x + (long)p * T_;

    float h[10];
    #pragma unroll
    for (int i = 0; i < 10; i++) h[i] = 0.0f;

    // Two-deep prefetch pipeline: token 2 ahead, embedding row 1 ahead.
    int tok_cur  = xrow[0];
    int tok_next = xrow[1];
    float4 ev4[5];
    {
        const float4* er = (const float4*)(emb + (long)tok_cur * E_);
        #pragma unroll
        for (int q = 0; q < 5; q++) ev4[q] = er[q];
    }

    #pragma unroll 1
    for (int t = 0; t < T_; t++) {
        const int tnn    = (t + 2 < T_) ? (t + 2) : (T_ - 1);
        const int tok_nn = xrow[tnn];
        float4 en4[5];
        {
            const float4* er = (const float4*)(emb + (long)tok_next * E_);
            #pragma unroll
            for (int q = 0; q < 5; q++) en4[q] = er[q];
        }

        float ev[20];
        #pragma unroll
        for (int q = 0; q < 5; q++) {
            ev[4*q+0] = ev4[q].x; ev[4*q+1] = ev4[q].y;
            ev[4*q+2] = ev4[q].z; ev[4*q+3] = ev4[q].w;
        }

        // acc = bh + e . Wxh   (my 10 output columns)
        float acc[10];
        #pragma unroll
        for (int jj = 0; jj < 10; jj++) {
            float a = sbh[j0 + jj];
            const float* row = sWxhT[j0 + jj];
            #pragma unroll
            for (int k = 0; k < E_; k++) a = fmaf(ev[k], row[k], a);
            acc[jj] = a;
        }

        // Exchange hidden halves with partner lane; normalize to canonical order.
        float oth[10];
        #pragma unroll
        for (int i = 0; i < 10; i++) oth[i] = __shfl_xor_sync(0xffffffffu, h[i], 1);
        float hA[10], hB[10];   // hA = h[0..9] global, hB = h[10..19] global
        #pragma unroll
        for (int i = 0; i < 10; i++) {
            hA[i] = half ? oth[i] : h[i];
            hB[i] = half ? h[i]   : oth[i];
        }

        // acc += h . Whh ; h = tanh(acc)
        #pragma unroll
        for (int jj = 0; jj < 10; jj++) {
            float a = acc[jj];
            const float* row = sWhhT[j0 + jj];
            #pragma unroll
            for (int i = 0; i < 10; i++) a = fmaf(hA[i], row[i],      a);
            #pragma unroll
            for (int i = 0; i < 10; i++) a = fmaf(hB[i], row[10 + i], a);
            // tanh(a) = 1 - 2/(exp(2a)+1): saturates correctly at +/-inf
            const float ex = __expf(2.0f * a);
            h[jj] = 1.0f - __fdividef(2.0f, ex + 1.0f);
        }

        #pragma unroll
        for (int q = 0; q < 5; q++) ev4[q] = en4[q];
        tok_next = tok_nn;
    }

    // Final exchange + epilogue (even lane computes the full softmax row)
    float oth[10];
    #pragma unroll
    for (int i = 0; i < 10; i++) oth[i] = __shfl_xor_sync(0xffffffffu, h[i], 1);

    if (half == 0) {
        const float sc = __fdividef(1.0f, 1.0f - drop[0]);  // inverted-dropout scale
        float hf[20];
        #pragma unroll
        for (int i = 0; i < 10; i++) { hf[i] = h[i] * sc; hf[10 + i] = oth[i] * sc; }

        float z[L_];
        #pragma unroll
        for (int l = 0; l < L_; l++) {
            float a = sbd[l];
            const float* row = sWdT[l];
            #pragma unroll
            for (int i = 0; i < H_; i++) a = fmaf(hf[i], row[i], a);
            z[l] = a;
        }
        float m = z[0];
        #pragma unroll
        for (int l = 1; l < L_; l++) m = fmaxf(m, z[l]);
        float s = 0.0f;
        #pragma unroll
        for (int l = 0; l < L_; l++) { z[l] = __expf(z[l] - m); s += z[l]; }
        const float inv = __fdividef(1.0f, s);
        float* o = out + (long)p * L_;
        #pragma unroll
        for (int l = 0; l < L_; l++) o[l] = z[l] * inv;
    }
}

extern "C" void kernel_launch(void* const* d_in, const int* in_sizes, int n_in,
                              void* d_out, int out_size)
{
    const int*   x    = (const int*)  d_in[0];
    const float* drop = (const float*)d_in[1];
    const float* emb  = (const float*)d_in[2];
    const float* Wxh  = (const float*)d_in[3];
    const float* Whh  = (const float*)d_in[4];
    const float* bh   = (const float*)d_in[5];
    const float* Wd   = (const float*)d_in[6];
    const float* bd   = (const float*)d_in[7];
    float* out = (float*)d_out;

    const int threads = 64;
    const int blocks  = (2 * B_) / threads;   // 512 blocks, exact
    wordvanilla_rnn_kernel<<<blocks, threads>>>(x, drop, emb, Wxh, Whh, bh, Wd, bd, out);
    (void)in_sizes; (void)n_in; (void)out_size;
}

// round 3
// speedup vs baseline: 1.0019x; 1.0003x over previous
#include <cuda_runtime.h>

#define B_  16384
#define T_  128
#define E_  20
#define H_  20
#define L_  15

// 2 lanes per batch row: lane parity 'half' owns hidden units [half*10, half*10+10).
// Weights live in shared memory, transposed so the K-loop is contiguous (LDS.128).
__global__ __launch_bounds__(64) void wordvanilla_rnn_kernel(
    const int*   __restrict__ x,      // [B, T]
    const float* __restrict__ drop,   // [1]
    const float* __restrict__ emb,    // [V, E]
    const float* __restrict__ Wxh,    // [E, H]
    const float* __restrict__ Whh,    // [H, H]
    const float* __restrict__ bh,     // [H]
    const float* __restrict__ Wd,     // [H, L]
    const float* __restrict__ bd,     // [L]
    float*       __restrict__ out)    // [B, L]
{
    __shared__ float sWxhT[H_][E_];   // sWxhT[j][k] = Wxh[k][j]
    __shared__ float sWhhT[H_][H_];   // sWhhT[j][i] = Whh[i][j]
    __shared__ float sWdT[L_][H_];    // sWdT[l][i]  = Wd[i][l]
    __shared__ float sbh[H_];
    __shared__ float sbd[16];

    const int tid = threadIdx.x;
    for (int idx = tid; idx < H_ * E_; idx += 64) {
        int j = idx / E_, k = idx % E_;
        sWxhT[j][k] = Wxh[k * H_ + j];
        sWhhT[j][k] = Whh[k * H_ + j];
    }
    for (int idx = tid; idx < L_ * H_; idx += 64) {
        int l = idx / H_, i = idx % H_;
        sWdT[l][i] = Wd[i * L_ + l];
    }
    if (tid < H_) sbh[tid] = bh[tid];
    if (tid < L_) sbd[tid] = bd[tid];
    __syncthreads();

    const int g    = blockIdx.x * 64 + tid;
    const int p    = g >> 1;        // batch row
    const int half = g & 1;         // which 10 hidden units this lane owns
    if (p >= B_) return;            // grid is exact; never taken
    const int j0 = half * 10;

    const int* xrow = x + (long)p * T_;

    float h[10];
    #pragma unroll
    for (int i = 0; i < 10; i++) h[i] = 0.0f;

    // Two-deep prefetch pipeline: token 2 ahead, embedding row 1 ahead.
    int tok_cur  = xrow[0];
    int tok_next = xrow[1];
    float4 ev4[5];
    {
        const float4* er = (const float4*)(emb + (long)tok_cur * E_);
        #pragma unroll
        for (int q = 0; q < 5; q++) ev4[q] = er[q];
    }

    #pragma unroll 1
    for (int t = 0; t < T_; t++) {
        const int tnn    = (t + 2 < T_) ? (t + 2) : (T_ - 1);
        const int tok_nn = xrow[tnn];
        float4 en4[5];
        {
            const float4* er = (const float4*)(emb + (long)tok_next * E_);
            #pragma unroll
            for (int q = 0; q < 5; q++) en4[q] = er[q];
        }

        float ev[20];
        #pragma unroll
        for (int q = 0; q < 5; q++) {
            ev[4*q+0] = ev4[q].x; ev[4*q+1] = ev4[q].y;
            ev[4*q+2] = ev4[q].z; ev[4*q+3] = ev4[q].w;
        }

        // acc = bh + e . Wxh   (my 10 output columns)
        float acc[10];
        #pragma unroll
        for (int jj = 0; jj < 10; jj++) {
            float a = sbh[j0 + jj];
            const float* row = sWxhT[j0 + jj];
            #pragma unroll
            for (int k = 0; k < E_; k++) a = fmaf(ev[k], row[k], a);
            acc[jj] = a;
        }

        // Exchange hidden halves with partner lane; normalize to canonical order.
        float oth[10];
        #pragma unroll
        for (int i = 0; i < 10; i++) oth[i] = __shfl_xor_sync(0xffffffffu, h[i], 1);
        float hA[10], hB[10];   // hA = h[0..9] global, hB = h[10..19] global
        #pragma unroll
        for (int i = 0; i < 10; i++) {
            hA[i] = half ? oth[i] : h[i];
            hB[i] = half ? h[i]   : oth[i];
        }

        // acc += h . Whh ; h = tanh(acc)
        #pragma unroll
        for (int jj = 0; jj < 10; jj++) {
            float a = acc[jj];
            const float* row = sWhhT[j0 + jj];
            #pragma unroll
            for (int i = 0; i < 10; i++) a = fmaf(hA[i], row[i],      a);
            #pragma unroll
            for (int i = 0; i < 10; i++) a = fmaf(hB[i], row[10 + i], a);
            // tanh(a) = 1 - 2/(exp(2a)+1): saturates correctly at +/-inf
            const float ex = __expf(2.0f * a);
            h[jj] = 1.0f - __fdividef(2.0f, ex + 1.0f);
        }

        #pragma unroll
        for (int q = 0; q < 5; q++) ev4[q] = en4[q];
        tok_next = tok_nn;
    }

    // Final exchange + epilogue (even lane computes the full softmax row)
    float oth[10];
    #pragma unroll
    for (int i = 0; i < 10; i++) oth[i] = __shfl_xor_sync(0xffffffffu, h[i], 1);

    if (half == 0) {
        const float sc = __fdividef(1.0f, 1.0f - drop[0]);  // inverted-dropout scale
        float hf[20];
        #pragma unroll
        for (int i = 0; i < 10; i++) { hf[i] = h[i] * sc; hf[10 + i] = oth[i] * sc; }

        float z[L_];
        #pragma unroll
        for (int l = 0; l < L_; l++) {
            float a = sbd[l];
            const float* row = sWdT[l];
            #pragma unroll
            for (int i = 0; i < H_; i++) a = fmaf(hf[i], row[i], a);
            z[l] = a;
        }
        float m = z[0];
        #pragma unroll
        for (int l = 1; l < L_; l++) m = fmaxf(m, z[l]);
        float s = 0.0f;
        #pragma unroll
        for (int l = 0; l < L_; l++) { z[l] = __expf(z[l] - m); s += z[l]; }
        const float inv = __fdividef(1.0f, s);
        float* o = out + (long)p * L_;
        #pragma unroll
        for (int l = 0; l < L_; l++) o[l] = z[l] * inv;
    }
}

extern "C" void kernel_launch(void* const* d_in, const int* in_sizes, int n_in,
                              void* d_out, int out_size)
{
    const int*   x    = (const int*)  d_in[0];
    const float* drop = (const float*)d_in[1];
    const float* emb  = (const float*)d_in[2];
    const float* Wxh  = (const float*)d_in[3];
    const float* Whh  = (const float*)d_in[4];
    const float* bh   = (const float*)d_in[5];
    const float* Wd   = (const float*)d_in[6];
    const float* bd   = (const float*)d_in[7];
    float* out = (float*)d_out;

    const int threads = 64;
    const int blocks  = (2 * B_) / threads;   // 512 blocks, exact
    wordvanilla_rnn_kernel<<<blocks, threads>>>(x, drop, emb, Wxh, Whh, bh, Wd, bd, out);
    (void)in_sizes; (void)n_in; (void)out_size;
}